// round 1
// baseline (speedup 1.0000x reference)
#include <cuda_runtime.h>

#define N_  128
#define D_  512
#define IC_ 32
#define OC_ 8
#define R_  4

// Precomputed softmax weights: layout [d][r][ic][oc]
__device__ float  g_w  [D_ * R_ * IC_ * OC_];   // w
__device__ float2 g_w22[D_ * R_ * IC_ * OC_];   // (w^2, w^2)

typedef unsigned long long u64;

__device__ __forceinline__ u64 pack2(float lo, float hi) {
    u64 r;
    asm("mov.b64 %0, {%1, %2};" : "=l"(r) : "f"(lo), "f"(hi));
    return r;
}
__device__ __forceinline__ void unpack2(u64 v, float& lo, float& hi) {
    asm("mov.b64 {%0, %1}, %2;" : "=f"(lo), "=f"(hi) : "l"(v));
}
// Packed dual FMA (Blackwell f32x2): d = a*b + c, lane-wise on two f32 halves
__device__ __forceinline__ u64 ffma2(u64 a, u64 b, u64 c) {
    u64 d;
    asm("fma.rn.f32x2 %0, %1, %2, %3;" : "=l"(d) : "l"(a), "l"(b), "l"(c));
    return d;
}

// ---------------------------------------------------------------------------
// Kernel A: softmax over IC for each (d, oc, r); one warp per group, lane = ic.
// Writes w and (w^2, w^2) in [d][r][ic][oc] layout for broadcast-friendly
// shared-memory access in kernel B.
// ---------------------------------------------------------------------------
__global__ __launch_bounds__(128) void softmax_w_kernel(const float* __restrict__ weights) {
    const int gid  = (blockIdx.x * blockDim.x + threadIdx.x) >> 5;
    const int lane = threadIdx.x & 31;
    if (gid >= D_ * OC_ * R_) return;
    const int d   = gid >> 5;        // / (OC_*R_) = 32
    const int rem = gid & 31;
    const int oc  = rem >> 2;
    const int r   = rem & 3;
    const int ic  = lane;

    float wr = weights[((d * IC_ + ic) * OC_ + oc) * R_ + r];
    float m = wr;
    #pragma unroll
    for (int s = 16; s; s >>= 1) m = fmaxf(m, __shfl_xor_sync(0xffffffffu, m, s));
    float e = __expf(wr - m);
    float ssum = e;
    #pragma unroll
    for (int s = 16; s; s >>= 1) ssum += __shfl_xor_sync(0xffffffffu, ssum, s);
    float w = e / ssum;

    const int idx = ((d * R_ + r) * IC_ + ic) * OC_ + oc;
    g_w[idx]   = w;
    g_w22[idx] = make_float2(w * w, w * w);
}

// ---------------------------------------------------------------------------
// Kernel B: fused main pass. Block = (d, 32 n's), 128 threads = 32 n x 4 r.
//   S1[oc] = sum_ic w      * exp(x)          -> log_probs = log(S1)
//   Sr[oc] = sum_ic w^2    * exp(x)^2   \
//   Sl[oc] = sum_ic w^2    * exp(v)     }-> log_vars = log(Sr + Sl)
// Sr/Sl fused into one packed f32x2 FMA chain.
// ---------------------------------------------------------------------------
__global__ __launch_bounds__(128) void main_kernel(const float* __restrict__ x,
                                                   const float* __restrict__ v,
                                                   float* __restrict__ out) {
    __shared__ float  s_x[32 * 129];          // padded: stride 129 -> conflict-free
    __shared__ float  s_v[32 * 129];
    __shared__ float  s_w[R_ * IC_ * OC_];    // 1024 floats
    __shared__ float2 s_w22[R_ * IC_ * OC_];  // 1024 float2 (8B aligned)

    const int t  = threadIdx.x;
    const int d  = blockIdx.y;
    const int n0 = blockIdx.x << 5;

    // ---- stage weights (coalesced) ----
    #pragma unroll
    for (int i = t; i < R_ * IC_ * OC_; i += 128) {
        s_w[i]   = g_w[d * 1024 + i];
        s_w22[i] = g_w22[d * 1024 + i];
    }

    // ---- stage x / vars: 32 n-chunks of 512B each, float4 global loads ----
    const float4* x4 = (const float4*)x;
    const float4* v4 = (const float4*)v;
    #pragma unroll
    for (int i = t; i < 1024; i += 128) {
        const int nl = i >> 5, pos = i & 31;
        const int gidx = ((n0 + nl) * D_ + d) * 32 + pos;   // float4 units
        float4 a = x4[gidx];
        float4 b = v4[gidx];
        const int sb = nl * 129 + pos * 4;
        s_x[sb + 0] = a.x; s_x[sb + 1] = a.y; s_x[sb + 2] = a.z; s_x[sb + 3] = a.w;
        s_v[sb + 0] = b.x; s_v[sb + 1] = b.y; s_v[sb + 2] = b.z; s_v[sb + 3] = b.w;
    }
    __syncthreads();

    // ---- compute: thread = (r = warp, n = lane) ----
    const int r = t >> 5;
    const int n = t & 31;

    u64   acc[OC_];   // packed (Sr, Sl)
    float s1[OC_];
    #pragma unroll
    for (int oc = 0; oc < OC_; oc++) { acc[oc] = 0ull; s1[oc] = 0.0f; }

    const float* xrow    = s_x + n * 129 + r;
    const float* vrow    = s_v + n * 129 + r;
    const float* wbase   = s_w + r * (IC_ * OC_);
    const u64*   w22base = (const u64*)(s_w22 + r * (IC_ * OC_));

    #pragma unroll 8
    for (int ic = 0; ic < IC_; ic++) {
        const float xv = xrow[ic * 4];
        const float vv = vrow[ic * 4];
        const float ex = __expf(xv);
        const float ev = __expf(vv);
        const u64 b = pack2(ex * ex, ev);
        #pragma unroll
        for (int oc = 0; oc < OC_; oc++) {
            const float w = wbase[ic * 8 + oc];        // warp-broadcast LDS
            const u64   a = w22base[ic * 8 + oc];      // warp-broadcast LDS.64
            acc[oc] = ffma2(a, b, acc[oc]);
            s1[oc]  = fmaf(w, ex, s1[oc]);
        }
    }
    __syncthreads();   // done reading s_x/s_v; reuse them as output staging

    // ---- finalize + stage outputs into smem (conflict-free [n][33] layout) ----
    #pragma unroll
    for (int oc = 0; oc < OC_; oc++) {
        float sr, sl;
        unpack2(acc[oc], sr, sl);
        const float lp = __logf(s1[oc]);
        const float lv = __logf(sr + sl);
        s_x[n * 33 + oc * 4 + r] = lp;
        s_v[n * 33 + oc * 4 + r] = lv;
    }
    __syncthreads();

    // ---- coalesced 128-bit stores ----
    float4* outp = (float4*)out;
    float4* outv = (float4*)(out + (size_t)N_ * D_ * OC_ * R_);
    #pragma unroll
    for (int i = t; i < 256; i += 128) {
        const int nl = i >> 3, q = i & 7;
        const int sb = nl * 33 + q * 4;
        float4 a, b;
        a.x = s_x[sb]; a.y = s_x[sb + 1]; a.z = s_x[sb + 2]; a.w = s_x[sb + 3];
        b.x = s_v[sb]; b.y = s_v[sb + 1]; b.z = s_v[sb + 2]; b.w = s_v[sb + 3];
        const int gidx = ((n0 + nl) * D_ + d) * 8 + q;     // float4 units
        outp[gidx] = a;
        outv[gidx] = b;
    }
}

extern "C" void kernel_launch(void* const* d_in, const int* in_sizes, int n_in,
                              void* d_out, int out_size) {
    const float* x       = (const float*)d_in[0];
    const float* vars    = (const float*)d_in[1];
    const float* weights = (const float*)d_in[2];
    float* out = (float*)d_out;

    // Kernel A: D*OC*R = 16384 warp-groups, 4 warps/block
    softmax_w_kernel<<<4096, 128>>>(weights);

    // Kernel B: grid (N/32, D)
    dim3 grid(N_ / 32, D_);
    main_kernel<<<grid, 128>>>(x, vars, out);
}

// round 3
// speedup vs baseline: 1.4947x; 1.4947x over previous
#include <cuda_runtime.h>

#define N_  128
#define D_  512
#define IC_ 32
#define OC_ 8
#define R_  4
#define PITCH  65   // transposed x/v staging pitch -> bank=(p+n)%32, conflict-free both ways
#define OPITCH 33   // output staging pitch

typedef unsigned long long u64;

__device__ __forceinline__ u64 pack2(float lo, float hi) {
    u64 r;
    asm("mov.b64 %0, {%1, %2};" : "=l"(r) : "f"(lo), "f"(hi));
    return r;
}
__device__ __forceinline__ void unpack2(u64 v, float& lo, float& hi) {
    asm("mov.b64 {%0, %1}, %2;" : "=f"(lo), "=f"(hi) : "l"(v));
}
// Packed dual FMA (Blackwell f32x2): d = a*b + c lane-wise
__device__ __forceinline__ u64 ffma2(u64 a, u64 b, u64 c) {
    u64 d;
    asm("fma.rn.f32x2 %0, %1, %2, %3;" : "=l"(d) : "l"(a), "l"(b), "l"(c));
    return d;
}

// ---------------------------------------------------------------------------
// One fused kernel. Block = (64 n's, one d). 256 threads = 8 warps =
// 2 n-halves x 4 r-warps; each thread owns one n.
// Phase 1: in-block softmax of this d's weights -> smem float4 (w_e,w_o,w2_e,w2_o)
// Phase 2: stage x/v transposed [p=ic*4+r][n] with pitch 65 (conflict-free)
// Phase 3: S1 = sum w*e^x, SR = sum w^2*e^2x, SL = sum w^2*e^v  (packed oc-pairs)
// Phase 4/5: logs -> smem transpose -> coalesced scalar stores
// ---------------------------------------------------------------------------
__global__ __launch_bounds__(256, 3) void fused_kernel(const float* __restrict__ x,
                                                       const float* __restrict__ v,
                                                       const float* __restrict__ weights,
                                                       float* __restrict__ out) {
    extern __shared__ float smem[];
    float*  s_x  = smem;                       // 128*65 = 8320 floats
    float*  s_v  = smem + 8320;                // 8320 floats
    float4* s_w4 = (float4*)(smem + 16640);    // 512 float4 (2048 floats), 16B aligned
    float*  s_m  = smem + 16640 + 2048;        // 32
    float*  s_is = s_m + 32;                   // 32
    // total 18752 floats = 75008 bytes

    const int t  = threadIdx.x;
    const int d  = blockIdx.y;
    const int n0 = blockIdx.x << 6;            // 0 or 64

    // ---- Phase 1: softmax over IC for this d ----
    const float* wd = weights + d * (IC_ * OC_ * R_);
    #pragma unroll
    for (int i = t; i < 1024; i += 256) s_x[i] = wd[i];   // raw weights in scratch
    __syncthreads();
    if (t < 32) {                               // group g = oc*4 + r = t
        float m = -1e30f;
        #pragma unroll
        for (int ic = 0; ic < 32; ic++) m = fmaxf(m, s_x[ic * 32 + t]);
        float s = 0.0f;
        #pragma unroll
        for (int ic = 0; ic < 32; ic++) s += __expf(s_x[ic * 32 + t] - m);
        s_m[t]  = m;
        s_is[t] = 1.0f / s;
    }
    __syncthreads();
    #pragma unroll
    for (int i = t; i < 1024; i += 256) {
        const int ic = i >> 5, oc = (i >> 2) & 7, r = i & 3;
        const int g  = oc * 4 + r;
        const float w = __expf(s_x[i] - s_m[g]) * s_is[g];
        float* dst = (float*)(s_w4 + ((r * 32 + ic) * 4 + (oc >> 1)));
        dst[oc & 1]       = w;
        dst[2 + (oc & 1)] = w * w;
    }
    __syncthreads();

    // ---- Phase 2: stage x/v transposed; thread owns row p = t&127, half jh = t>>7 ----
    {
        const int p  = t & 127;
        const int jh = t >> 7;                  // 0 or 1 -> j in [jh*32, jh*32+32)
        const size_t base = (size_t)(n0 + jh * 32) * (D_ * 128) + (size_t)d * 128 + p;
        const float* xg = x + base;
        const float* vg = v + base;
        float* dx = s_x + p * PITCH + jh * 32;
        float* dv = s_v + p * PITCH + jh * 32;
        #pragma unroll 8
        for (int j = 0; j < 32; j++) {
            dx[j] = xg[(size_t)j * (D_ * 128)];
            dv[j] = vg[(size_t)j * (D_ * 128)];
        }
    }
    __syncthreads();

    // ---- Phase 3: main accumulation. warp = (half, r); lane n consecutive ----
    const int half = t >> 7;                    // 0/1
    const int r    = (t >> 5) & 3;
    const int n    = (t & 31) + half * 32;

    u64 a1[4], aR[4], aL[4];
    #pragma unroll
    for (int o = 0; o < 4; o++) { a1[o] = 0ull; aR[o] = 0ull; aL[o] = 0ull; }

    const float* xr = s_x + r * PITCH + n;
    const float* vr = s_v + r * PITCH + n;
    const u64*   wb = (const u64*)s_w4 + (size_t)r * 32 * 8;

    #pragma unroll 8
    for (int ic = 0; ic < 32; ic++) {
        const int off = ic * 4 * PITCH;
        const float xv = xr[off];
        const float vv = vr[off];
        const float e = __expf(xv);
        const float f = __expf(vv);
        const float q = e * e;
        const u64 bS = pack2(e, e);
        const u64 bR = pack2(q, q);
        const u64 bL = pack2(f, f);
        const u64* wi = wb + ic * 8;
        #pragma unroll
        for (int o = 0; o < 4; o++) {
            const u64 wlo = wi[o * 2];        // (w_{2o}, w_{2o+1})   broadcast LDS.64
            const u64 whi = wi[o * 2 + 1];    // (w^2_{2o}, w^2_{2o+1})
            a1[o] = ffma2(wlo, bS, a1[o]);
            aR[o] = ffma2(whi, bR, aR[o]);
            aL[o] = ffma2(whi, bL, aL[o]);
        }
    }
    __syncthreads();   // done reading s_x/s_v; reuse as output staging

    // ---- Phase 4: finalize logs into transpose staging ----
    #pragma unroll
    for (int o = 0; o < 4; o++) {
        float s1a, s1b, sra, srb, sla, slb;
        unpack2(a1[o], s1a, s1b);
        unpack2(aR[o], sra, srb);
        unpack2(aL[o], sla, slb);
        s_x[n * OPITCH + (2 * o) * 4 + r]     = __logf(s1a);
        s_x[n * OPITCH + (2 * o + 1) * 4 + r] = __logf(s1b);
        s_v[n * OPITCH + (2 * o) * 4 + r]     = __logf(sra + sla);
        s_v[n * OPITCH + (2 * o + 1) * 4 + r] = __logf(srb + slb);
    }
    __syncthreads();

    // ---- Phase 5: coalesced scalar stores ----
    {
        float* op = out + (size_t)n0 * (D_ * OC_ * R_) + (size_t)d * 32;
        float* ov = op + (size_t)N_ * D_ * OC_ * R_;
        const int c = t & 31;
        #pragma unroll
        for (int k = 0; k < 8; k++) {
            const int nl = (t >> 5) + 8 * k;
            op[(size_t)nl * (D_ * 32) + c] = s_x[nl * OPITCH + c];
            ov[(size_t)nl * (D_ * 32) + c] = s_v[nl * OPITCH + c];
        }
    }
}

extern "C" void kernel_launch(void* const* d_in, const int* in_sizes, int n_in,
                              void* d_out, int out_size) {
    const float* x       = (const float*)d_in[0];
    const float* vars    = (const float*)d_in[1];
    const float* weights = (const float*)d_in[2];
    float* out = (float*)d_out;

    cudaFuncSetAttribute(fused_kernel, cudaFuncAttributeMaxDynamicSharedMemorySize, 75008);
    dim3 grid(2, 512);
    fused_kernel<<<grid, 256, 75008>>>(x, vars, weights, out);
}

// round 5
// speedup vs baseline: 1.5197x; 1.0167x over previous
#include <cuda_runtime.h>

#define N_  128
#define D_  512
#define IC_ 32
#define OC_ 8
#define R_  4
#define PITCH  65   // transposed x/v staging pitch -> bank=(p+n)%32, conflict-free both ways
#define OPITCH 65   // output staging pitch ([c][n] layout, n in 0..63 -> pitch must be >=64; 65 = conflict-free)

typedef unsigned long long u64;

__device__ __forceinline__ u64 pack2(float lo, float hi) {
    u64 r;
    asm("mov.b64 %0, {%1, %2};" : "=l"(r) : "f"(lo), "f"(hi));
    return r;
}
__device__ __forceinline__ void unpack2(u64 v, float& lo, float& hi) {
    asm("mov.b64 {%0, %1}, %2;" : "=f"(lo), "=f"(hi) : "l"(v));
}
// Packed dual FMA (Blackwell f32x2): d = a*b + c lane-wise
__device__ __forceinline__ u64 ffma2(u64 a, u64 b, u64 c) {
    u64 d;
    asm("fma.rn.f32x2 %0, %1, %2, %3;" : "=l"(d) : "l"(a), "l"(b), "l"(c));
    return d;
}

// ---------------------------------------------------------------------------
// One fused kernel. Block = (64 n's, one d). 256 threads = 8 warps =
// 2 n-halves x 4 r-warps; each thread owns one n.
// Phase 1: in-block softmax of this d's weights -> smem float4 (w_e,w_o,w2_e,w2_o)
// Phase 2: stage x/v transposed [p=ic*4+r][n] with pitch 65 (conflict-free)
// Phase 3: S1 = sum w*e^x, SR = sum w^2*e^2x, SL = sum w^2*e^v  (packed oc-pairs;
//          ONE broadcast LDS.128 per oc-pair per ic)
// Phase 4: logs -> smem staged [c][n] pitch 65 (1-wf STS)
// Phase 5: 4x conflict-free LDS + STG.128 coalesced stores
// ---------------------------------------------------------------------------
__global__ __launch_bounds__(256, 3) void fused_kernel(const float* __restrict__ x,
                                                       const float* __restrict__ v,
                                                       const float* __restrict__ weights,
                                                       float* __restrict__ out) {
    extern __shared__ float smem[];
    float*  s_x  = smem;                       // 128*65 = 8320 floats
    float*  s_v  = smem + 8320;                // 8320 floats
    float4* s_w4 = (float4*)(smem + 16640);    // 512 float4 (2048 floats), 16B aligned
    float*  s_m  = smem + 16640 + 2048;        // 32
    float*  s_is = s_m + 32;                   // 32
    // total 18752 floats = 75008 bytes

    const int t  = threadIdx.x;
    const int d  = blockIdx.y;
    const int n0 = blockIdx.x << 6;            // 0 or 64

    // ---- Phase 1: softmax over IC for this d ----
    const float* wd = weights + d * (IC_ * OC_ * R_);
    #pragma unroll
    for (int i = t; i < 1024; i += 256) s_x[i] = wd[i];   // raw weights in scratch
    __syncthreads();
    if (t < 32) {                               // group g = oc*4 + r = t
        float m = -1e30f;
        #pragma unroll
        for (int ic = 0; ic < 32; ic++) m = fmaxf(m, s_x[ic * 32 + t]);
        float s = 0.0f;
        #pragma unroll
        for (int ic = 0; ic < 32; ic++) s += __expf(s_x[ic * 32 + t] - m);
        s_m[t]  = m;
        s_is[t] = 1.0f / s;
    }
    __syncthreads();
    #pragma unroll
    for (int i = t; i < 1024; i += 256) {
        const int ic = i >> 5, oc = (i >> 2) & 7, r = i & 3;
        const int g  = oc * 4 + r;
        const float w = __expf(s_x[i] - s_m[g]) * s_is[g];
        float* dst = (float*)(s_w4 + ((r * 32 + ic) * 4 + (oc >> 1)));
        dst[oc & 1]       = w;
        dst[2 + (oc & 1)] = w * w;
    }
    __syncthreads();

    // ---- Phase 2: stage x/v transposed; thread owns row p = t&127, half jh = t>>7 ----
    {
        const int p  = t & 127;
        const int jh = t >> 7;                  // 0 or 1 -> j in [jh*32, jh*32+32)
        const size_t base = (size_t)(n0 + jh * 32) * (D_ * 128) + (size_t)d * 128 + p;
        const float* xg = x + base;
        const float* vg = v + base;
        float* dx = s_x + p * PITCH + jh * 32;
        float* dv = s_v + p * PITCH + jh * 32;
        #pragma unroll 8
        for (int j = 0; j < 32; j++) {
            dx[j] = xg[(size_t)j * (D_ * 128)];
            dv[j] = vg[(size_t)j * (D_ * 128)];
        }
    }
    __syncthreads();

    // ---- Phase 3: main accumulation. warp = (half, r); lane n consecutive ----
    const int half = t >> 7;                    // 0/1
    const int r    = (t >> 5) & 3;
    const int n    = (t & 31) + half * 32;

    u64 a1[4], aR[4], aL[4];
    #pragma unroll
    for (int o = 0; o < 4; o++) { a1[o] = 0ull; aR[o] = 0ull; aL[o] = 0ull; }

    const float*  xr = s_x + r * PITCH + n;
    const float*  vr = s_v + r * PITCH + n;
    const float4* wb = s_w4 + (size_t)r * 32 * 4;

    #pragma unroll 8
    for (int ic = 0; ic < 32; ic++) {
        const int off = ic * 4 * PITCH;
        const float xv = xr[off];
        const float vv = vr[off];
        const float e = __expf(xv);
        const float f = __expf(vv);
        const float q = e * e;
        const u64 bS = pack2(e, e);
        const u64 bR = pack2(q, q);
        const u64 bL = pack2(f, f);
        const float4* wi = wb + ic * 4;
        #pragma unroll
        for (int o = 0; o < 4; o++) {
            const float4 w4 = wi[o];             // ONE broadcast LDS.128: (w_e,w_o,w2_e,w2_o)
            const u64 wlo = pack2(w4.x, w4.y);
            const u64 whi = pack2(w4.z, w4.w);
            a1[o] = ffma2(wlo, bS, a1[o]);
            aR[o] = ffma2(whi, bR, aR[o]);
            aL[o] = ffma2(whi, bL, aL[o]);
        }
    }
    __syncthreads();   // done reading s_x/s_v; reuse as output staging

    // ---- Phase 4: finalize logs into [c][n] staging, pitch 65 (bank=(c+n)%32, 1 wf) ----
    #pragma unroll
    for (int o = 0; o < 4; o++) {
        float s1a, s1b, sra, srb, sla, slb;
        unpack2(a1[o], s1a, s1b);
        unpack2(aR[o], sra, srb);
        unpack2(aL[o], sla, slb);
        const int c0 = (2 * o) * 4 + r;          // oc = 2o
        const int c1 = (2 * o + 1) * 4 + r;      // oc = 2o+1
        s_x[c0 * OPITCH + n] = __logf(s1a);
        s_x[c1 * OPITCH + n] = __logf(s1b);
        s_v[c0 * OPITCH + n] = __logf(sra + sla);
        s_v[c1 * OPITCH + n] = __logf(srb + slb);
    }
    __syncthreads();

    // ---- Phase 5: gather 4 c's per thread, STG.128 coalesced ----
    {
        float* op = out + (size_t)n0 * (D_ * OC_ * R_) + (size_t)d * 32;
        float* ov = op + (size_t)N_ * D_ * OC_ * R_;
        #pragma unroll
        for (int m = 0; m < 2; m++) {
            const int i  = t + 256 * m;
            const int q  = i & 7;                // float4 index within 32-col row
            const int nl = i >> 3;               // 0..63
            float4 a, b;
            a.x = s_x[(4 * q + 0) * OPITCH + nl];
            a.y = s_x[(4 * q + 1) * OPITCH + nl];
            a.z = s_x[(4 * q + 2) * OPITCH + nl];
            a.w = s_x[(4 * q + 3) * OPITCH + nl];
            b.x = s_v[(4 * q + 0) * OPITCH + nl];
            b.y = s_v[(4 * q + 1) * OPITCH + nl];
            b.z = s_v[(4 * q + 2) * OPITCH + nl];
            b.w = s_v[(4 * q + 3) * OPITCH + nl];
            *(float4*)(op + (size_t)nl * (D_ * 32) + 4 * q) = a;
            *(float4*)(ov + (size_t)nl * (D_ * 32) + 4 * q) = b;
        }
    }
}

extern "C" void kernel_launch(void* const* d_in, const int* in_sizes, int n_in,
                              void* d_out, int out_size) {
    const float* x       = (const float*)d_in[0];
    const float* vars    = (const float*)d_in[1];
    const float* weights = (const float*)d_in[2];
    float* out = (float*)d_out;

    cudaFuncSetAttribute(fused_kernel, cudaFuncAttributeMaxDynamicSharedMemorySize, 75008);
    dim3 grid(2, 512);
    fused_kernel<<<grid, 256, 75008>>>(x, vars, weights, out);
}

// round 6
// speedup vs baseline: 1.5269x; 1.0048x over previous
#include <cuda_runtime.h>

#define N_  128
#define D_  512
#define IC_ 32
#define OC_ 8
#define R_  4
#define OPITCH 65   // output staging pitch ([c][n], n<64 -> conflict-free)

// shared layout (float offsets):
//  s_x : [0, 8192)        x staging, swizzled pitch 64
//  s_v : [8192, 16384)    v staging
//  w4  : [16384, 18432)   packed weights (w_e,w_o,w2_e,w2_o) per (r,ic,ocpair)
//  P   : [18432, 18696)   8*33 reduction partials
//  sm  : [18696, 18728)   per-group max
//  sis : [18728, 18760)   per-group 1/sum
#define SMEM_FLOATS 18760
#define SMEM_BYTES  (SMEM_FLOATS * 4)

typedef unsigned long long u64;

__device__ __forceinline__ u64 pack2(float lo, float hi) {
    u64 r; asm("mov.b64 %0, {%1, %2};" : "=l"(r) : "f"(lo), "f"(hi)); return r;
}
__device__ __forceinline__ void unpack2(u64 v, float& lo, float& hi) {
    asm("mov.b64 {%0, %1}, %2;" : "=f"(lo), "=f"(hi) : "l"(v));
}
__device__ __forceinline__ u64 ffma2(u64 a, u64 b, u64 c) {
    u64 d; asm("fma.rn.f32x2 %0, %1, %2, %3;" : "=l"(d) : "l"(a), "l"(b), "l"(c)); return d;
}
__device__ __forceinline__ unsigned smem_u32(const void* p) {
    unsigned r;
    asm("{ .reg .u64 t; cvta.to.shared.u64 t, %1; cvt.u32.u64 %0, t; }" : "=r"(r) : "l"(p));
    return r;
}
__device__ __forceinline__ void cp4(unsigned dst, const float* src) {
    asm volatile("cp.async.ca.shared.global [%0], [%1], 4;" :: "r"(dst), "l"(src));
}

__global__ __launch_bounds__(256, 3) void fused_kernel(const float* __restrict__ x,
                                                       const float* __restrict__ v,
                                                       const float* __restrict__ weights,
                                                       float* __restrict__ out) {
    extern __shared__ float smem[];
    float* s_x  = smem;
    float* s_v  = smem + 8192;
    float* s_w4f = smem + 16384;
    float* s_P  = smem + 18432;
    float* s_m  = smem + 18696;
    float* s_is = smem + 18728;

    const int t  = threadIdx.x;
    const int d  = blockIdx.y;
    const int n0 = blockIdx.x << 6;

    // ---- P1a: weight LDG first (4 coalesced loads, in flight during cp.async burst) ----
    const float* wd = weights + d * (IC_ * OC_ * R_);
    float raw[4];
    #pragma unroll
    for (int k = 0; k < 4; k++) raw[k] = wd[t + 256 * k];

    // ---- P0: fire-and-forget async staging of x/v (swizzled pitch-64) ----
    {
        const int p  = t & 127;
        const int jh = t >> 7;
        const size_t gbase = (size_t)(n0 + jh * 32) * (D_ * 128) + (size_t)d * 128 + p;
        const float* xg = x + gbase;
        const float* vg = v + gbase;
        const unsigned sx = smem_u32(s_x);
        const unsigned sv = smem_u32(s_v);
        #pragma unroll 8
        for (int j = 0; j < 32; j++) {
            const int el = p * 64 + (((jh * 32 + j) + p) & 63);
            cp4(sx + el * 4, xg + (size_t)j * (D_ * 128));
            cp4(sv + el * 4, vg + (size_t)j * (D_ * 128));
        }
        asm volatile("cp.async.commit_group;");
    }

    // ---- P1: parallel softmax over IC per group g = oc*4+r (raw stays in regs) ----
    const int w  = t >> 5;     // warp id
    const int ln = t & 31;     // lane = group id g
    // B1: local max of 4 ic's
    {
        const float m4 = fmaxf(fmaxf(raw[0], raw[1]), fmaxf(raw[2], raw[3]));
        s_P[w * 33 + ln] = m4;
    }
    __syncthreads();
    // B2: reduce 8 warps' partials
    if (t < 32) {
        float m = s_P[t];
        #pragma unroll
        for (int q = 1; q < 8; q++) m = fmaxf(m, s_P[q * 33 + t]);
        s_m[t] = m;
    }
    __syncthreads();
    // B3: exp + local sum
    float e4[4];
    {
        const float mg = s_m[ln];
        float s = 0.0f;
        #pragma unroll
        for (int k = 0; k < 4; k++) { e4[k] = __expf(raw[k] - mg); s += e4[k]; }
        s_P[w * 33 + ln] = s;
    }
    __syncthreads();
    // B4: reduce sums -> 1/sum
    if (t < 32) {
        float s = s_P[t];
        #pragma unroll
        for (int q = 1; q < 8; q++) s += s_P[q * 33 + t];
        s_is[t] = 1.0f / s;
    }
    __syncthreads();
    // E: write packed (w, w^2) float4 table
    {
        const float isr = s_is[ln];
        const int oc = ln >> 2, rr = ln & 3;
        #pragma unroll
        for (int k = 0; k < 4; k++) {
            const int ic = (t >> 5) + 8 * k;
            const float wv = e4[k] * isr;
            const int base = ((rr * 32 + ic) * 4 + (oc >> 1)) * 4 + (oc & 1);
            s_w4f[base]     = wv;
            s_w4f[base + 2] = wv * wv;
        }
    }
    asm volatile("cp.async.wait_group 0;");
    __syncthreads();

    // ---- F: main accumulation. warp = (half, r); lane n ----
    const int half = t >> 7;
    const int r    = (t >> 5) & 3;
    const int n    = (t & 31) + half * 32;

    u64 a1[4], aR[4], aL[4];
    #pragma unroll
    for (int o = 0; o < 4; o++) { a1[o] = 0ull; aR[o] = 0ull; aL[o] = 0ull; }

    const float4* wb = (const float4*)s_w4f + (size_t)r * 128;
    const int nb = n + r;

    #pragma unroll 8
    for (int ic = 0; ic < 32; ic++) {
        const int row = (ic * 4 + r) * 64;
        const int idx = (nb + 4 * ic) & 63;
        const float xv = s_x[row + idx];
        const float vv = s_v[row + idx];
        const float e = __expf(xv);
        const float f = __expf(vv);
        const float q = e * e;
        const u64 bS = pack2(e, e);
        const u64 bR = pack2(q, q);
        const u64 bL = pack2(f, f);
        const float4* wi = wb + ic * 4;
        #pragma unroll
        for (int o = 0; o < 4; o++) {
            const float4 w4 = wi[o];             // ONE broadcast LDS.128
            a1[o] = ffma2(pack2(w4.x, w4.y), bS, a1[o]);
            aR[o] = ffma2(pack2(w4.z, w4.w), bR, aR[o]);
            aL[o] = ffma2(pack2(w4.z, w4.w), bL, aL[o]);
        }
    }
    __syncthreads();   // done reading s_x/s_v; reuse as output staging

    // ---- Phase 4: logs -> [c][n] staging (pitch 65, 1-wf) ----
    #pragma unroll
    for (int o = 0; o < 4; o++) {
        float s1a, s1b, sra, srb, sla, slb;
        unpack2(a1[o], s1a, s1b);
        unpack2(aR[o], sra, srb);
        unpack2(aL[o], sla, slb);
        const int c0 = (2 * o) * 4 + r;
        const int c1 = (2 * o + 1) * 4 + r;
        s_x[c0 * OPITCH + n] = __logf(s1a);
        s_x[c1 * OPITCH + n] = __logf(s1b);
        s_v[c0 * OPITCH + n] = __logf(sra + sla);
        s_v[c1 * OPITCH + n] = __logf(srb + slb);
    }
    __syncthreads();

    // ---- Phase 5: gather 4 c's, STG.128 coalesced ----
    {
        float* op = out + (size_t)n0 * (D_ * OC_ * R_) + (size_t)d * 32;
        float* ov = op + (size_t)N_ * D_ * OC_ * R_;
        #pragma unroll
        for (int m = 0; m < 2; m++) {
            const int i  = t + 256 * m;
            const int q  = i & 7;
            const int nl = i >> 3;
            float4 a, b;
            a.x = s_x[(4 * q + 0) * OPITCH + nl];
            a.y = s_x[(4 * q + 1) * OPITCH + nl];
            a.z = s_x[(4 * q + 2) * OPITCH + nl];
            a.w = s_x[(4 * q + 3) * OPITCH + nl];
            b.x = s_v[(4 * q + 0) * OPITCH + nl];
            b.y = s_v[(4 * q + 1) * OPITCH + nl];
            b.z = s_v[(4 * q + 2) * OPITCH + nl];
            b.w = s_v[(4 * q + 3) * OPITCH + nl];
            *(float4*)(op + (size_t)nl * (D_ * 32) + 4 * q) = a;
            *(float4*)(ov + (size_t)nl * (D_ * 32) + 4 * q) = b;
        }
    }
}

extern "C" void kernel_launch(void* const* d_in, const int* in_sizes, int n_in,
                              void* d_out, int out_size) {
    const float* x       = (const float*)d_in[0];
    const float* vars    = (const float*)d_in[1];
    const float* weights = (const float*)d_in[2];
    float* out = (float*)d_out;

    cudaFuncSetAttribute(fused_kernel, cudaFuncAttributeMaxDynamicSharedMemorySize, SMEM_BYTES);
    dim3 grid(2, 512);
    fused_kernel<<<grid, 256, SMEM_BYTES>>>(x, vars, weights, out);
}